// round 17
// baseline (speedup 1.0000x reference)
#include <cuda_runtime.h>
#include <cuda_fp16.h>
#include <cstdint>

#define NB 4096
#define NT 32               // 32x32 grid of 128x128 tiles
#define NTILES 528          // upper-triangle tiles

// Ph = 0.35355*18*p, Qh = (0.35355/18)*q  ->  Ph*Qh == 0.125*p*q exactly.
// Stored params are P8 = 0.125p and Q = q, so:
#define PH_SCALE 50.9117f    // 0.35355339*18/0.125
#define QH_SCALE 0.01964186f // 0.35355339/18

// ---------------- device scratch (static: no allocation allowed) ----------------
// C row (256 e4m3 bytes): [x | -2m | 1/v | m/v] (64B each), x = v + m^2
// "D" row = C rotated by 128 bytes; 128B-chunk c of D = chunk 1-c of C.
__device__ uint8_t g_C[(size_t)NB * 256];
__device__ float  g_A8[NB];    // 0.125*a_i - 8
__device__ float  g_P8[NB];    // 0.125*p_i
__device__ float  g_Q[NB];     // 1/(p_i + 1e-8)
__device__ double g_pos, g_neg;
__device__ unsigned g_arrive = 0, g_done = 0;
__device__ volatile unsigned g_release = 0;

static __device__ __forceinline__ uint32_t smem_u32(const void* p) {
    uint32_t a;
    asm("{ .reg .u64 t; cvta.to.shared.u64 t, %1; cvt.u32.u64 %0, t; }" : "=r"(a) : "l"(p));
    return a;
}
static __device__ __forceinline__ float frcp(float x) {
    float r; asm("rcp.approx.f32 %0, %1;" : "=f"(r) : "f"(x)); return r;
}
static __device__ __forceinline__ float ftanh(float x) {
    float r; asm("tanh.approx.f32 %0, %1;" : "=f"(r) : "f"(x)); return r;
}
static __device__ __forceinline__ __half2 htanh2(__half2 x) {
    __half2 r;
    asm("tanh.approx.f16x2 %0, %1;" : "=r"(*(uint32_t*)&r) : "r"(*(uint32_t*)&x));
    return r;
}
static __device__ __forceinline__ void cpa16(uint32_t dst, const void* src) {
    asm volatile("cp.async.ca.shared.global [%0], [%1], 16;" :: "r"(dst), "l"(src));
}
static __device__ __forceinline__ uint32_t pack_e4m3(float s0, float s1, float s2, float s3) {
    uint32_t r;
    asm("{ .reg .b16 a, b;\n\t"
        "cvt.rn.satfinite.e4m3x2.f32 a, %2, %1;\n\t"
        "cvt.rn.satfinite.e4m3x2.f32 b, %4, %3;\n\t"
        "mov.b32 %0, {a, b}; }"
        : "=r"(r) : "f"(s0), "f"(s1), "f"(s2), "f"(s3));
    return r;
}

// smem: A chunk 128x128B (16KB, XOR-swizzled 16B granules), B chunk 128x128B (16KB),
//       fp32 row params 2KB, half row/col params 2KB, scratch
#define AS_OFF 0
#define BS_OFF 16384
#define PAR_OFF 32768
#define RED_OFF 36864
#define SMEM_BYTES 36928

static __device__ __forceinline__ uint32_t swoff(int r, int g) {
    return (uint32_t)(r * 128 + (((g) ^ (r & 7)) << 4));
}

// ---- stage one 128B K chunk: A = C(I) chunk c (128 rows), B = C(J) chunk 1-c (128 rows)
static __device__ __forceinline__ void stage_chunk(
    uint32_t sbase, const char* baseI, const char* baseJ, int c, int tid)
{
    int pa = c * 128, pb = 128 - c * 128;
    #pragma unroll
    for (int p = 0; p < 8; p++) {
        int idx = tid + p * 128, r = idx >> 3, g = idx & 7;
        cpa16(sbase + AS_OFF + swoff(r, g), baseI + r * 256 + pa + g * 16);
        cpa16(sbase + BS_OFF + swoff(r, g), baseJ + r * 256 + pb + g * 16);
    }
    asm volatile("cp.async.commit_group;" ::: "memory");
}

// ---- one 128B K chunk of the 128x128 FP8 GEMM; warp tile 64x64, f16 accumulators ----
static __device__ __forceinline__ void gemm_chunk(
    uint32_t csA, uint32_t csB, int lane, int warp_m, int warp_n,
    uint32_t (&acc)[4][8][2])
{
    #pragma unroll
    for (int s = 0; s < 4; s++) {
        uint32_t af[4][4];
        #pragma unroll
        for (int mi = 0; mi < 4; mi++) {
            int r = warp_m * 64 + mi * 16 + (lane & 15);
            uint32_t addr = csA + swoff(r, 2 * s + (lane >> 4));
            asm volatile("ldmatrix.sync.aligned.m8n8.x4.shared.b16 {%0,%1,%2,%3}, [%4];"
                         : "=r"(af[mi][0]), "=r"(af[mi][1]), "=r"(af[mi][2]), "=r"(af[mi][3])
                         : "r"(addr));
        }
        #pragma unroll
        for (int ni = 0; ni < 8; ni++) {
            int rb = warp_n * 64 + ni * 8 + (lane & 7);
            uint32_t addr = csB + swoff(rb, 2 * s + ((lane >> 3) & 1));
            uint32_t b0, b1;
            asm volatile("ldmatrix.sync.aligned.m8n8.x2.shared.b16 {%0,%1}, [%2];"
                         : "=r"(b0), "=r"(b1) : "r"(addr));
            #pragma unroll
            for (int mi = 0; mi < 4; mi++) {
                asm volatile(
                    "mma.sync.aligned.m16n8k32.row.col.f16.e4m3.e4m3.f16 "
                    "{%0,%1}, {%2,%3,%4,%5}, {%6,%7}, {%0,%1};"
                    : "+r"(acc[mi][ni][0]), "+r"(acc[mi][ni][1])
                    : "r"(af[mi][0]), "r"(af[mi][1]), "r"(af[mi][2]), "r"(af[mi][3]),
                      "r"(b0), "r"(b1));
            }
        }
    }
}

static __device__ __forceinline__ void decode_tile(int ft, int& I, int& J) {
    I = 0;
    while (ft >= NT - I) { ft -= NT - I; I++; }
    J = I + ft;
}

__global__ void __launch_bounds__(128, 4) mega_kernel(
    const float* __restrict__ mu, const float* __restrict__ var,
    const int* __restrict__ labels, float* __restrict__ out)
{
    extern __shared__ char smem[];
    uint32_t sbase = smem_u32(smem);
    int tid = threadIdx.x, lane = tid & 31, wid = tid >> 5;

    // ================= phase 0: prep =================
    for (int row0 = blockIdx.x * 8; row0 < NB; row0 += gridDim.x * 8) {
        int row = row0 + (tid >> 4), l16 = tid & 15;
        float4 m4 = ((const float4*)(mu  + (size_t)row * 64))[l16];
        float4 v4 = ((const float4*)(var + (size_t)row * 64))[l16];
        float m[4] = {m4.x, m4.y, m4.z, m4.w};
        float v[4] = {v4.x, v4.y, v4.z, v4.w};
        float x[4], n2m[4], iv[4], w[4];
        float pv = 1.0f, av = 0.0f;
        #pragma unroll
        for (int d = 0; d < 4; d++) {
            iv[d]  = frcp(v[d]);
            x[d]   = v[d] + m[d] * m[d];
            n2m[d] = -2.0f * m[d];
            w[d]   = m[d] * iv[d];
            pv *= v[d];
            av = fmaf(m[d] * m[d], iv[d], av);
        }
        uint32_t* crow = (uint32_t*)(g_C + (size_t)row * 256);
        crow[0 * 16 + l16] = pack_e4m3(x[0], x[1], x[2], x[3]);
        crow[1 * 16 + l16] = pack_e4m3(n2m[0], n2m[1], n2m[2], n2m[3]);
        crow[2 * 16 + l16] = pack_e4m3(iv[0], iv[1], iv[2], iv[3]);
        crow[3 * 16 + l16] = pack_e4m3(w[0], w[1], w[2], w[3]);
        #pragma unroll
        for (int off = 1; off < 16; off <<= 1) {
            pv *= __shfl_xor_sync(0xffffffffu, pv, off);
            av += __shfl_xor_sync(0xffffffffu, av, off);
        }
        if (l16 == 0) {
            g_A8[row] = 0.125f * av - 8.0f;
            g_P8[row] = 0.125f * pv;
            g_Q[row]  = frcp(pv + 1e-8f);
        }
    }

    // ================= device-wide barrier (all CTAs resident) =================
    __syncthreads();
    if (tid == 0) {
        unsigned target = g_release + 1;
        __threadfence();
        unsigned a = atomicAdd(&g_arrive, 1);
        if (a == gridDim.x - 1) {
            g_arrive = 0;
            g_pos = 0.0; g_neg = 0.0;
            __threadfence();
            atomicAdd((unsigned*)&g_release, 1);
        } else {
            while (g_release < target) __nanosleep(64);
        }
        __threadfence();
    }
    __syncthreads();

    // ================= phase 1: full 128x128 tiles, static single wave =================
    float* rowAf = (float*)(smem + PAR_OFF);      // 128 fp32
    float* rowPf = rowAf + 128;
    float* rowQf = rowPf + 128;
    int*   rowLi = (int*)(rowQf + 128);
    __half* rowAh = (__half*)(rowLi + 128);       // 128 half each
    __half* rowPh = rowAh + 128;
    __half* rowQh = rowPh + 128;
    __half* rowLh = rowQh + 128;
    __half* colAh = rowLh + 128;
    __half* colPh = colAh + 128;
    __half* colQh = colPh + 128;
    __half* colLh = colQh + 128;
    float* red = (float*)(smem + RED_OFF);

    uint32_t csA = sbase + AS_OFF, csB = sbase + BS_OFF;
    int warp_m = wid & 1, warp_n = wid >> 1;
    float pos = 0.0f, neg = 0.0f;

    for (int t = blockIdx.x; t < NTILES; t += gridDim.x) {
        int I, J;
        decode_tile(t, I, J);
        int Ibase = I * 128, Jbase = J * 128;
        const char* baseI = (const char*)g_C + (size_t)Ibase * 256;
        const char* baseJ = (const char*)g_C + (size_t)Jbase * 256;
        const bool diag = (I == J);

        __syncthreads();   // previous tile's epilogue done with smem

        stage_chunk(sbase, baseI, baseJ, 0, tid);
        // params; Ph*Qh == 0.125*p_i*q_j exactly (centered scaling, no floor clamp)
        {
            float fa = g_A8[Ibase + tid], fp = g_P8[Ibase + tid], fq = g_Q[Ibase + tid];
            int   li = labels[Ibase + tid];
            rowAf[tid] = fa; rowPf[tid] = fp; rowQf[tid] = fq; rowLi[tid] = li;
            rowAh[tid] = __float2half(fa);
            rowPh[tid] = __float2half(fminf(fp * PH_SCALE, 60000.0f));
            rowQh[tid] = __float2half(fminf(fq * QH_SCALE, 60000.0f));
            rowLh[tid] = __float2half((float)li);
            float ga = g_A8[Jbase + tid], gp = g_P8[Jbase + tid], gq = g_Q[Jbase + tid];
            int   lj = labels[Jbase + tid];
            colAh[tid] = __float2half(ga);
            colPh[tid] = __float2half(fminf(gp * PH_SCALE, 60000.0f));
            colQh[tid] = __float2half(fminf(gq * QH_SCALE, 60000.0f));
            colLh[tid] = __float2half((float)lj);
        }
        asm volatile("cp.async.wait_group 0;" ::: "memory");
        __syncthreads();

        uint32_t acc[4][8][2];
        #pragma unroll
        for (int mi = 0; mi < 4; mi++)
            #pragma unroll
            for (int ni = 0; ni < 8; ni++) { acc[mi][ni][0] = 0u; acc[mi][ni][1] = 0u; }

        gemm_chunk(csA, csB, lane, warp_m, warp_n, acc);
        __syncthreads();
        stage_chunk(sbase, baseI, baseJ, 1, tid);
        asm volatile("cp.async.wait_group 0;" ::: "memory");
        __syncthreads();
        gemm_chunk(csA, csB, lane, warp_m, warp_n, acc);

        if (!diag) {
            // half2 epilogue with fp32 spill every 8 half2-adds (sums stay <= 8)
            const __half2 k0125 = __floats2half2_rn(0.125f, 0.125f);
            const __half2 khalf = __floats2half2_rn(0.5f, 0.5f);
            #pragma unroll
            for (int mi = 0; mi < 4; mi++) {
                #pragma unroll
                for (int k = 0; k < 2; k++) {
                    int r = warp_m * 64 + mi * 16 + (lane >> 2) + k * 8;
                    __half2 RA = __half2half2(rowAh[r]);
                    __half2 RP = __half2half2(rowPh[r]);
                    __half2 RQ = __half2half2(rowQh[r]);
                    __half2 RL = __half2half2(rowLh[r]);
                    __half2 sum2 = __floats2half2_rn(0.0f, 0.0f);
                    __half2 pos2 = sum2;
                    #pragma unroll
                    for (int ni = 0; ni < 8; ni++) {
                        int c0 = warp_n * 64 + ni * 8 + (lane & 3) * 2;
                        __half2 v2 = *(__half2*)&acc[mi][ni][k];
                        __half2 AJ = *(__half2*)(colAh + c0);
                        __half2 PJ = *(__half2*)(colPh + c0);
                        __half2 QJ = *(__half2*)(colQh + c0);
                        __half2 LJ = *(__half2*)(colLh + c0);
                        __half2 s2 = __hfma2(v2, k0125, RA);
                        s2 = __hadd2(s2, AJ);
                        s2 = __hfma2(RP, QJ, s2);
                        s2 = __hfma2(PJ, RQ, s2);
                        __half2 sg = __hfma2(htanh2(s2), khalf, khalf);
                        __half2 m2 = __heq2(RL, LJ);
                        sum2 = __hadd2(sum2, sg);
                        pos2 = __hfma2(m2, sg, pos2);
                    }
                    float2 sf = __half22float2(sum2);
                    float2 pf = __half22float2(pos2);
                    float ps = pf.x + pf.y, ss = sf.x + sf.y;
                    pos += ps;
                    neg += ss - ps;
                }
            }
        } else {
            // exact fp32 path for the 32 diagonal tiles (col params == row params)
            #pragma unroll
            for (int mi = 0; mi < 4; mi++) {
                #pragma unroll
                for (int k = 0; k < 2; k++) {
                    int r = warp_m * 64 + mi * 16 + (lane >> 2) + k * 8;
                    float RA = rowAf[r], RP = rowPf[r], RQ = rowQf[r];
                    int   RL = rowLi[r];
                    #pragma unroll
                    for (int ni = 0; ni < 8; ni++) {
                        int c0 = warp_n * 64 + ni * 8 + (lane & 3) * 2;
                        float2 f = __half22float2(*(__half2*)&acc[mi][ni][k]);
                        #pragma unroll
                        for (int e = 0; e < 2; e++) {
                            int c = c0 + e;
                            float vv = e ? f.y : f.x;
                            float s = fmaf(vv, 0.125f, RA);
                            s += rowAf[c];
                            s = fmaf(RP, rowQf[c], s);
                            s = fmaf(rowPf[c], RQ, s);
                            float sg = fmaf(ftanh(s), 0.5f, 0.5f);
                            if (c > r) {
                                if (RL == rowLi[c]) pos += sg; else neg += sg;
                            }
                        }
                    }
                }
            }
        }
    }

    // ================= final reduce + output by last CTA =================
    #pragma unroll
    for (int off = 16; off; off >>= 1) {
        pos += __shfl_xor_sync(0xffffffffu, pos, off);
        neg += __shfl_xor_sync(0xffffffffu, neg, off);
    }
    __syncthreads();
    if (lane == 0) { red[wid] = pos; red[4 + wid] = neg; }
    __syncthreads();
    if (tid == 0) {
        double P = 0.0, Nn = 0.0;
        #pragma unroll
        for (int w = 0; w < 4; w++) { P += (double)red[w]; Nn += (double)red[4 + w]; }
        atomicAdd(&g_pos, P);
        atomicAdd(&g_neg, Nn);
        __threadfence();
        unsigned d = atomicAdd(&g_done, 1);
        if (d == gridDim.x - 1) {
            double TP = 2.0 * atomicAdd(&g_pos, 0.0);
            double TN = 2.0 * atomicAdd(&g_neg, 0.0);
            const double inv = 1.0 / ((double)NB * (double)NB);
            out[0] = (float)(TP * inv);
            out[1] = (float)(TN * inv);
            out[2] = (float)TP;
            out[3] = (float)TN;
            g_done = 0;
        }
    }
}

// ---------------- launcher ----------------
extern "C" void kernel_launch(void* const* d_in, const int* in_sizes, int n_in,
                              void* d_out, int out_size) {
    (void)in_sizes; (void)n_in; (void)out_size;
    const float* mu     = (const float*)d_in[0];
    const float* var    = (const float*)d_in[1];
    const int*   labels = (const int*)d_in[2];
    float* out = (float*)d_out;

    cudaFuncSetAttribute(mega_kernel, cudaFuncAttributeMaxDynamicSharedMemorySize,
                         SMEM_BYTES);
    int occ = 0, sms = 0, dev = 0;
    cudaGetDevice(&dev);
    cudaOccupancyMaxActiveBlocksPerMultiprocessor(&occ, mega_kernel, 128, SMEM_BYTES);
    cudaDeviceGetAttribute(&sms, cudaDevAttrMultiProcessorCount, dev);
    int grid = occ * sms;
    if (grid > NTILES) grid = NTILES;
    if (grid < 1) grid = 1;

    mega_kernel<<<grid, 128, SMEM_BYTES>>>(mu, var, labels, out);
}